// round 7
// baseline (speedup 1.0000x reference)
#include <cuda_runtime.h>

// Problem constants: T=4, L=4, N=2048, E=65536, H=64, C=2
#define TT 4
#define LL 4
#define NN 2048
#define EE 65536
#define HH 64
#define TL (TT*LL)

// ---------------- device scratch ----------------
// stride-8 rows (32B aligned): [0..3]={w*xs0,w*xs1,w*ea0,w*ea1}, [4]=w
// 32B stride keeps each node's atomics in its own LTS sector (R6 lesson).
// Zero at module load; node_kernel restores zeros every call.
__device__ float g_sums[TL * NN * 8];
__device__ float g_val[TT * 2 * LL * NN];   // [T][2*L*N]

// ---------------- K1: edge pass (R4 version — 1 edge/thread, own alpha coefs) ----------------
__global__ void __launch_bounds__(256) edge_kernel(const float* __restrict__ x,
                                                   const float* __restrict__ ea,
                                                   const int* __restrict__ src,
                                                   const int* __restrict__ tgt,
                                                   const float* __restrict__ Wq,
                                                   const float* __restrict__ bq,
                                                   const float* __restrict__ Wk,
                                                   const float* __restrict__ bk,
                                                   const float* __restrict__ We)
{
    __shared__ float sc[4][16];         // coefA for (t, l=0..3); t fixed per block

    int tid = threadIdx.x;
    int wid = tid >> 5, lane = tid & 31;
    int idx = blockIdx.x * 256 + tid;   // 0 .. T*E-1
    int t = (blockIdx.x * 256) >> 16;   // constant per block (256 | E)

    // Warps 0..3: compute coefA for tl = t*4 + wid
    if (wid < 4) {
        int tl = t * LL + wid;
        const float* wq0 = Wq + (size_t)tl * 2 * HH;
        const float* wq1 = wq0 + HH;
        const float* bqp = bq + (size_t)tl * HH;
        float q0a = wq0[lane], q0b = wq0[lane + 32];
        float q1a = wq1[lane], q1b = wq1[lane + 32];
        float bba = bqp[lane], bbb = bqp[lane + 32];

        const float* Xs[5];
        Xs[0] = Wk + (size_t)tl * 2 * HH;
        Xs[1] = Xs[0] + HH;
        Xs[2] = We + (size_t)tl * 2 * HH;
        Xs[3] = Xs[2] + HH;
        Xs[4] = bk + (size_t)tl * HH;

        float pa[15];
#pragma unroll
        for (int k = 0; k < 5; k++) {
            float xa = Xs[k][lane], xb = Xs[k][lane + 32];
            pa[3*k + 0] = q0a * xa + q0b * xb;
            pa[3*k + 1] = q1a * xa + q1b * xb;
            pa[3*k + 2] = bba * xa + bbb * xb;
        }
#pragma unroll
        for (int off = 16; off > 0; off >>= 1)
#pragma unroll
            for (int i = 0; i < 15; i++)
                pa[i] += __shfl_down_sync(0xffffffffu, pa[i], off);
        if (lane == 0) {
#pragma unroll
            for (int i = 0; i < 15; i++) sc[wid][i] = pa[i];
            sc[wid][15] = 0.0f;
        }
    }
    __syncthreads();

    int s = src[idx];
    int g = tgt[idx];
    float xs0 = x[2 * s], xs1 = x[2 * s + 1];
    float ea0 = ea[2 * idx], ea1 = ea[2 * idx + 1];
    int tn = t * NN + g;
    float xt0 = x[2 * tn], xt1 = x[2 * tn + 1];

#pragma unroll
    for (int l = 0; l < LL; l++) {
        const float* c = sc[l];
        float A0 = fmaf(c[0],  xt0, fmaf(c[1],  xt1, c[2]));
        float A1 = fmaf(c[3],  xt0, fmaf(c[4],  xt1, c[5]));
        float A2 = fmaf(c[6],  xt0, fmaf(c[7],  xt1, c[8]));
        float A3 = fmaf(c[9],  xt0, fmaf(c[10], xt1, c[11]));
        float A4 = fmaf(c[12], xt0, fmaf(c[13], xt1, c[14]));
        float alpha = (A0 * xs0 + A1 * xs1 + A2 * ea0 + A3 * ea1 + A4) * 0.125f;
        float w = expf(alpha);   // |alpha| is O(1): shift-free softmax is safe
        float* sm = &g_sums[((t * LL + l) * NN + g) * 8];
        asm volatile("red.global.add.v4.f32 [%0], {%1, %2, %3, %4};"
                     :: "l"(sm), "f"(w * xs0), "f"(w * xs1),
                        "f"(w * ea0), "f"(w * ea1)
                     : "memory");
        atomicAdd(sm + 4, w);
    }
}

// ---------------- K2: node pass (R4 version — own half-sum coefs, restores zeros) ----------------
__global__ void __launch_bounds__(256) node_kernel(const float* __restrict__ x,
                                                   const float* __restrict__ Wv,
                                                   const float* __restrict__ bv,
                                                   const float* __restrict__ We,
                                                   const float* __restrict__ Wsk,
                                                   const float* __restrict__ bsk)
{
    __shared__ float h[16];             // coefH for this block's tl

    int tid = threadIdx.x;
    int idx = blockIdx.x * 256 + tid;   // 0 .. T*L*N-1
    int tl = (blockIdx.x * 256) >> 11;  // constant per block (256 | N)
    int t = tl >> 2;
    int l = tl & 3;
    int n = idx & (NN - 1);

    if (tid < 32) {
        int lane = tid;
        const float* Ys[8];
        Ys[0] = Wv + (size_t)tl * 2 * HH;
        Ys[1] = Ys[0] + HH;
        Ys[2] = We + (size_t)tl * 2 * HH;
        Ys[3] = Ys[2] + HH;
        Ys[4] = bv + (size_t)tl * HH;
        Ys[5] = Wsk + (size_t)tl * 2 * HH;
        Ys[6] = Ys[5] + HH;
        Ys[7] = bsk + (size_t)tl * HH;

        float ph[16];
#pragma unroll
        for (int k = 0; k < 8; k++) {
            ph[k]     = Ys[k][lane];           // low half (h<32)
            ph[8 + k] = Ys[k][lane + 32];      // high half
        }
#pragma unroll
        for (int off = 16; off > 0; off >>= 1)
#pragma unroll
            for (int i = 0; i < 16; i++)
                ph[i] += __shfl_down_sync(0xffffffffu, ph[i], off);
        if (lane == 0)
#pragma unroll
            for (int i = 0; i < 16; i++) h[i] = ph[i];
    }
    __syncthreads();

    float* smp = &g_sums[idx * 8];
    float4 v = *reinterpret_cast<float4*>(smp);
    float s4 = smp[4];

    // restore zeros for next replay
    *reinterpret_cast<float4*>(smp) = make_float4(0.f, 0.f, 0.f, 0.f);
    smp[4] = 0.f;

    float inv = 1.0f / (s4 + 1e-16f);
    float S0 = v.x * inv, S1 = v.y * inv, S2 = v.z * inv, S3 = v.w * inv;
    float S4 = s4 * inv;

    int tn = t * NN + n;
    float xt0 = x[2 * tn], xt1 = x[2 * tn + 1];

    float P = S0*h[0] + S1*h[1] + S2*h[2] + S3*h[3] + S4*h[4]
            + xt0*h[5] + xt1*h[6] + h[7];
    float Q = S0*h[8] + S1*h[9] + S2*h[10] + S3*h[11] + S4*h[12]
            + xt0*h[13] + xt1*h[14] + h[15];

    int vo = t * (2 * LL * NN) + 2 * (l * NN + n);
    g_val[vo]     = P;
    g_val[vo + 1] = Q;
}

// ---------------- K3: GEMV — 8 warps x 4 rows/warp (32 rows/block), __ldcs stream ----------------
__global__ void __launch_bounds__(256) gemv_kernel(const float* __restrict__ Wfc,
                                                   const float* __restrict__ bfc,
                                                   float* __restrict__ out)
{
    const int t = blockIdx.y;
    const int rowBase = blockIdx.x * 32;
    __shared__ float4 sv[1024];                    // 16 KB chunk of val

    int tid = threadIdx.x;
    int lane = tid & 31;
    int w = tid >> 5;                              // warp 0..7

    // 4 rows per warp: rowBase + w + 8*k
    const float4* W[4];
#pragma unroll
    for (int k = 0; k < 4; k++)
        W[k] = reinterpret_cast<const float4*>(
            Wfc + ((size_t)(t * 4096 + rowBase + w + 8 * k)) * 16384);

    const float4* val4 = reinterpret_cast<const float4*>(g_val + t * (2 * LL * NN));

    float4 a0 = make_float4(0.f, 0.f, 0.f, 0.f);
    float4 a1 = make_float4(0.f, 0.f, 0.f, 0.f);
    float4 a2 = make_float4(0.f, 0.f, 0.f, 0.f);
    float4 a3 = make_float4(0.f, 0.f, 0.f, 0.f);

#pragma unroll
    for (int c = 0; c < 4; c++) {
        for (int j = tid; j < 1024; j += 256)
            sv[j] = val4[c * 1024 + j];
        __syncthreads();

        const int base = c * 1024;
#pragma unroll 4
        for (int j = lane; j < 1024; j += 32) {
            float4 v  = sv[j];
            float4 w0 = __ldcs(&W[0][base + j]);   // streaming: no-reuse 1GB scan
            float4 w1 = __ldcs(&W[1][base + j]);
            float4 w2 = __ldcs(&W[2][base + j]);
            float4 w3 = __ldcs(&W[3][base + j]);
            a0.x = fmaf(w0.x, v.x, a0.x); a0.y = fmaf(w0.y, v.y, a0.y);
            a0.z = fmaf(w0.z, v.z, a0.z); a0.w = fmaf(w0.w, v.w, a0.w);
            a1.x = fmaf(w1.x, v.x, a1.x); a1.y = fmaf(w1.y, v.y, a1.y);
            a1.z = fmaf(w1.z, v.z, a1.z); a1.w = fmaf(w1.w, v.w, a1.w);
            a2.x = fmaf(w2.x, v.x, a2.x); a2.y = fmaf(w2.y, v.y, a2.y);
            a2.z = fmaf(w2.z, v.z, a2.z); a2.w = fmaf(w2.w, v.w, a2.w);
            a3.x = fmaf(w3.x, v.x, a3.x); a3.y = fmaf(w3.y, v.y, a3.y);
            a3.z = fmaf(w3.z, v.z, a3.z); a3.w = fmaf(w3.w, v.w, a3.w);
        }
        __syncthreads();
    }

    float s0 = (a0.x + a0.y) + (a0.z + a0.w);
    float s1 = (a1.x + a1.y) + (a1.z + a1.w);
    float s2 = (a2.x + a2.y) + (a2.z + a2.w);
    float s3 = (a3.x + a3.y) + (a3.z + a3.w);
#pragma unroll
    for (int off = 16; off > 0; off >>= 1) {
        s0 += __shfl_down_sync(0xffffffffu, s0, off);
        s1 += __shfl_down_sync(0xffffffffu, s1, off);
        s2 += __shfl_down_sync(0xffffffffu, s2, off);
        s3 += __shfl_down_sync(0xffffffffu, s3, off);
    }
    if (lane == 0) {
        int o = t * 4096 + rowBase + w;
        out[o]      = s0 + bfc[o];
        out[o + 8]  = s1 + bfc[o + 8];
        out[o + 16] = s2 + bfc[o + 16];
        out[o + 24] = s3 + bfc[o + 24];
    }
}

// ---------------- launch: 3 kernels, single stream ----------------
extern "C" void kernel_launch(void* const* d_in, const int* in_sizes, int n_in,
                              void* d_out, int out_size)
{
    const float* x    = (const float*)d_in[0];
    const float* ea   = (const float*)d_in[1];
    const int*   src  = (const int*)  d_in[2];
    const int*   tgt  = (const int*)  d_in[3];
    const float* Wq   = (const float*)d_in[4];
    const float* bq   = (const float*)d_in[5];
    const float* Wk   = (const float*)d_in[6];
    const float* bk   = (const float*)d_in[7];
    const float* Wv   = (const float*)d_in[8];
    const float* bv   = (const float*)d_in[9];
    const float* We   = (const float*)d_in[10];
    const float* Wsk  = (const float*)d_in[11];
    const float* bsk  = (const float*)d_in[12];
    const float* Wfc  = (const float*)d_in[13];
    const float* bfc  = (const float*)d_in[14];
    float* out = (float*)d_out;

    edge_kernel<<<(TT * EE) / 256, 256>>>(x, ea, src, tgt, Wq, bq, Wk, bk, We);
    node_kernel<<<(TL * NN) / 256, 256>>>(x, Wv, bv, We, Wsk, bsk);
    gemv_kernel<<<dim3(128, TT), 256>>>(Wfc, bfc, out);
}

// round 8
// speedup vs baseline: 1.1904x; 1.1904x over previous
#include <cuda_runtime.h>

// Problem constants: T=4, L=4, N=2048, E=65536, H=64, C=2
#define TT 4
#define LL 4
#define NN 2048
#define EE 65536
#define HH 64
#define TL (TT*LL)

// Block layout inside the fused kernel (dependencies only point to lower indices):
#define EDGE_PER_L 1024
#define NODE_PER_L 32
#define GROUP (EDGE_PER_L + NODE_PER_L)     // 1056
#define GEMV_BLOCKS 1024
#define TOTAL_BLOCKS (LL * GROUP + GEMV_BLOCKS)  // 5248

// ---------------- device scratch ----------------
// stride-8 rows (32B aligned): [0..3]={w*xs0,w*xs1,w*ea0,w*ea1}, [4]=w
// Zero at module load; node role restores zeros every call.
__device__ float g_sums[TL * NN * 8];
__device__ float g_val[TT * 2 * LL * NN];   // [T][2*L*N]
__device__ unsigned g_edgeCnt[LL];
__device__ unsigned g_nodeCnt[LL];

__global__ void reset_kernel() {
    if (threadIdx.x < LL) {
        g_edgeCnt[threadIdx.x] = 0;
        g_nodeCnt[threadIdx.x] = 0;
    }
}

__device__ __forceinline__ unsigned ld_acquire(unsigned* p) {
    unsigned v;
    asm volatile("ld.acquire.gpu.u32 %0, [%1];" : "=r"(v) : "l"(p) : "memory");
    return v;
}

// ---------------- fused kernel ----------------
__global__ void __launch_bounds__(256) fused_kernel(
    const float* __restrict__ x,
    const float* __restrict__ ea,
    const int* __restrict__ src,
    const int* __restrict__ tgt,
    const float* __restrict__ Wq,  const float* __restrict__ bq,
    const float* __restrict__ Wk,  const float* __restrict__ bk,
    const float* __restrict__ Wv,  const float* __restrict__ bv,
    const float* __restrict__ We,
    const float* __restrict__ Wsk, const float* __restrict__ bsk,
    const float* __restrict__ Wfc, const float* __restrict__ bfc,
    float* __restrict__ out)
{
    __shared__ __align__(16) float s_raw[4096];   // 16 KB: gemv staging / coef scratch
    int tid = threadIdx.x;
    int b = blockIdx.x;

    if (b < LL * GROUP) {
        int l = b / GROUP;
        int r = b - l * GROUP;

        if (r < EDGE_PER_L) {
            // ---------------- EDGE role: layer l, 256 edges ----------------
            float* sc = s_raw;                 // coefA[16] for (t, l)
            int wid = tid >> 5, lane = tid & 31;
            int idx = r * 256 + tid;           // 0 .. T*E-1
            int t = r >> 8;                    // 256 blocks per type

            if (wid == 0) {
                int tl = t * LL + l;
                const float* wq0 = Wq + (size_t)tl * 2 * HH;
                const float* wq1 = wq0 + HH;
                const float* bqp = bq + (size_t)tl * HH;
                float q0a = wq0[lane], q0b = wq0[lane + 32];
                float q1a = wq1[lane], q1b = wq1[lane + 32];
                float bba = bqp[lane], bbb = bqp[lane + 32];

                const float* Xs[5];
                Xs[0] = Wk + (size_t)tl * 2 * HH;
                Xs[1] = Xs[0] + HH;
                Xs[2] = We + (size_t)tl * 2 * HH;
                Xs[3] = Xs[2] + HH;
                Xs[4] = bk + (size_t)tl * HH;

                float pa[15];
#pragma unroll
                for (int k = 0; k < 5; k++) {
                    float xa = Xs[k][lane], xb = Xs[k][lane + 32];
                    pa[3*k + 0] = q0a * xa + q0b * xb;
                    pa[3*k + 1] = q1a * xa + q1b * xb;
                    pa[3*k + 2] = bba * xa + bbb * xb;
                }
#pragma unroll
                for (int off = 16; off > 0; off >>= 1)
#pragma unroll
                    for (int i = 0; i < 15; i++)
                        pa[i] += __shfl_down_sync(0xffffffffu, pa[i], off);
                if (lane == 0) {
#pragma unroll
                    for (int i = 0; i < 15; i++) sc[i] = pa[i];
                    sc[15] = 0.0f;
                }
            }
            __syncthreads();

            int s = src[idx];
            int g = tgt[idx];
            float xs0 = x[2 * s], xs1 = x[2 * s + 1];
            float ea0 = ea[2 * idx], ea1 = ea[2 * idx + 1];
            int tn = t * NN + g;
            float xt0 = x[2 * tn], xt1 = x[2 * tn + 1];

            float A0 = fmaf(sc[0],  xt0, fmaf(sc[1],  xt1, sc[2]));
            float A1 = fmaf(sc[3],  xt0, fmaf(sc[4],  xt1, sc[5]));
            float A2 = fmaf(sc[6],  xt0, fmaf(sc[7],  xt1, sc[8]));
            float A3 = fmaf(sc[9],  xt0, fmaf(sc[10], xt1, sc[11]));
            float A4 = fmaf(sc[12], xt0, fmaf(sc[13], xt1, sc[14]));
            float alpha = (A0 * xs0 + A1 * xs1 + A2 * ea0 + A3 * ea1 + A4) * 0.125f;
            float w = expf(alpha);   // |alpha| is O(1): shift-free softmax is safe
            float* sm = &g_sums[((t * LL + l) * NN + g) * 8];
            asm volatile("red.global.add.v4.f32 [%0], {%1, %2, %3, %4};"
                         :: "l"(sm), "f"(w * xs0), "f"(w * xs1),
                            "f"(w * ea0), "f"(w * ea1)
                         : "memory");
            atomicAdd(sm + 4, w);

            __threadfence();
            __syncthreads();
            if (tid == 0) atomicAdd(&g_edgeCnt[l], 1u);
        } else {
            // ---------------- NODE role: layer l, 256 nodes ----------------
            float* h = s_raw;                  // coefH[16] for (t, l)
            int m = r - EDGE_PER_L;            // 0..31
            int item = m * 256 + tid;          // 0 .. T*N-1
            int t = item >> 11;                // constant per block (256 | N)
            int n = item & (NN - 1);
            int tl = t * LL + l;

            if (tid < 32) {
                int lane = tid;
                const float* Ys[8];
                Ys[0] = Wv + (size_t)tl * 2 * HH;
                Ys[1] = Ys[0] + HH;
                Ys[2] = We + (size_t)tl * 2 * HH;
                Ys[3] = Ys[2] + HH;
                Ys[4] = bv + (size_t)tl * HH;
                Ys[5] = Wsk + (size_t)tl * 2 * HH;
                Ys[6] = Ys[5] + HH;
                Ys[7] = bsk + (size_t)tl * HH;

                float ph[16];
#pragma unroll
                for (int k = 0; k < 8; k++) {
                    ph[k]     = Ys[k][lane];
                    ph[8 + k] = Ys[k][lane + 32];
                }
#pragma unroll
                for (int off = 16; off > 0; off >>= 1)
#pragma unroll
                    for (int i = 0; i < 16; i++)
                        ph[i] += __shfl_down_sync(0xffffffffu, ph[i], off);
                if (lane == 0)
#pragma unroll
                    for (int i = 0; i < 16; i++) h[i] = ph[i];
            }
            __syncthreads();

            // wait for all edge blocks of this layer
            if (tid == 0)
                while (ld_acquire(&g_edgeCnt[l]) < EDGE_PER_L) __nanosleep(64);
            __syncthreads();

            float* smp = &g_sums[(tl * NN + n) * 8];
            float4 v = *reinterpret_cast<float4*>(smp);
            float s4 = smp[4];

            // restore zeros for next replay
            *reinterpret_cast<float4*>(smp) = make_float4(0.f, 0.f, 0.f, 0.f);
            smp[4] = 0.f;

            float inv = 1.0f / (s4 + 1e-16f);
            float S0 = v.x * inv, S1 = v.y * inv, S2 = v.z * inv, S3 = v.w * inv;
            float S4 = s4 * inv;

            int tn = t * NN + n;
            float xt0 = x[2 * tn], xt1 = x[2 * tn + 1];

            float P = S0*h[0] + S1*h[1] + S2*h[2] + S3*h[3] + S4*h[4]
                    + xt0*h[5] + xt1*h[6] + h[7];
            float Q = S0*h[8] + S1*h[9] + S2*h[10] + S3*h[11] + S4*h[12]
                    + xt0*h[13] + xt1*h[14] + h[15];

            int vo = t * (2 * LL * NN) + 2 * (l * NN + n);
            g_val[vo]     = P;
            g_val[vo + 1] = Q;

            __threadfence();
            __syncthreads();
            if (tid == 0) atomicAdd(&g_nodeCnt[l], 1u);
        }
    } else {
        // ---------------- GEMV role: R5 shape (8 warps x 2 rows) ----------------
        int g = b - LL * GROUP;            // 0..1023
        const int t = g >> 8;
        const int rowBase = (g & 255) * 16;
        float4* sv = reinterpret_cast<float4*>(s_raw);   // 1024 float4

        int lane = tid & 31;
        int w = tid >> 5;
        int r0 = rowBase + w;
        int r1 = rowBase + 8 + w;

        const float4* val4 = reinterpret_cast<const float4*>(g_val + t * (2 * LL * NN));
        const float4* W0 = reinterpret_cast<const float4*>(Wfc + ((size_t)(t * 4096 + r0)) * 16384);
        const float4* W1 = reinterpret_cast<const float4*>(Wfc + ((size_t)(t * 4096 + r1)) * 16384);

        float4 a0 = make_float4(0.f, 0.f, 0.f, 0.f);
        float4 a1 = make_float4(0.f, 0.f, 0.f, 0.f);

#pragma unroll
        for (int c = 0; c < 4; c++) {
            // chunk c == val layer c: wait until its node blocks are done
            if (tid == 0)
                while (ld_acquire(&g_nodeCnt[c]) < NODE_PER_L) __nanosleep(64);
            __syncthreads();

            for (int j = tid; j < 1024; j += 256)
                sv[j] = val4[c * 1024 + j];
            __syncthreads();

            const int base = c * 1024;
#pragma unroll 8
            for (int j = lane; j < 1024; j += 32) {
                float4 v  = sv[j];
                float4 w0 = __ldcs(&W0[base + j]);   // streaming: no-reuse 1GB scan
                float4 w1 = __ldcs(&W1[base + j]);
                a0.x = fmaf(w0.x, v.x, a0.x);
                a0.y = fmaf(w0.y, v.y, a0.y);
                a0.z = fmaf(w0.z, v.z, a0.z);
                a0.w = fmaf(w0.w, v.w, a0.w);
                a1.x = fmaf(w1.x, v.x, a1.x);
                a1.y = fmaf(w1.y, v.y, a1.y);
                a1.z = fmaf(w1.z, v.z, a1.z);
                a1.w = fmaf(w1.w, v.w, a1.w);
            }
            __syncthreads();
        }

        float s0 = (a0.x + a0.y) + (a0.z + a0.w);
        float s1 = (a1.x + a1.y) + (a1.z + a1.w);
#pragma unroll
        for (int off = 16; off > 0; off >>= 1) {
            s0 += __shfl_down_sync(0xffffffffu, s0, off);
            s1 += __shfl_down_sync(0xffffffffu, s1, off);
        }
        if (lane == 0) {
            out[t * 4096 + r0] = s0 + bfc[t * 4096 + r0];
            out[t * 4096 + r1] = s1 + bfc[t * 4096 + r1];
        }
    }
}

// ---------------- launch ----------------
extern "C" void kernel_launch(void* const* d_in, const int* in_sizes, int n_in,
                              void* d_out, int out_size)
{
    const float* x    = (const float*)d_in[0];
    const float* ea   = (const float*)d_in[1];
    const int*   src  = (const int*)  d_in[2];
    const int*   tgt  = (const int*)  d_in[3];
    const float* Wq   = (const float*)d_in[4];
    const float* bq   = (const float*)d_in[5];
    const float* Wk   = (const float*)d_in[6];
    const float* bk   = (const float*)d_in[7];
    const float* Wv   = (const float*)d_in[8];
    const float* bv   = (const float*)d_in[9];
    const float* We   = (const float*)d_in[10];
    const float* Wsk  = (const float*)d_in[11];
    const float* bsk  = (const float*)d_in[12];
    const float* Wfc  = (const float*)d_in[13];
    const float* bfc  = (const float*)d_in[14];
    float* out = (float*)d_out;

    reset_kernel<<<1, 32>>>();
    fused_kernel<<<TOTAL_BLOCKS, 256>>>(x, ea, src, tgt, Wq, bq, Wk, bk,
                                        Wv, bv, We, Wsk, bsk, Wfc, bfc, out);
}

// round 12
// speedup vs baseline: 1.3020x; 1.0937x over previous
#include <cuda_runtime.h>

// Problem constants: T=4, L=4, N=2048, E=65536, H=64, C=2
#define TT 4
#define LL 4
#define NN 2048
#define EE 65536
#define HH 64
#define TL (TT*LL)

// ---------------- device scratch ----------------
// stride-8 rows (32B): [0]=sum(w*p), [1]=sum(w*q), [2]=sum(w), [3]=0 (v4 pad), [4..7] unused.
// One 32B LTS sector per (t,l,n) row -> single red.v4 per edge-layer, no sector sharing.
// Zero at module load; node_kernel restores zeros every call.
__device__ float g_sums[TL * NN * 8];
__device__ float g_val[TT * 2 * LL * NN];   // [T][2*L*N]

// ---------------- K1: edge pass — folded coefs, ONE red.v4 per edge-layer ----------------
// Per (t,l):
//   coefA[15]: alpha = (A0(xt)*xs0 + A1(xt)*xs1 + A2(xt)*ea0 + A3(xt)*ea1 + A4(xt))/8
//   coefP[5]:  p_e = h0*xs0+h1*xs1+h2*ea0+h3*ea1+h4  (low-half col sums of Wv/We/bv)
//   coefQ[5]:  q_e = same with high-half sums
__global__ void __launch_bounds__(256) edge_kernel(const float* __restrict__ x,
                                                   const float* __restrict__ ea,
                                                   const int* __restrict__ src,
                                                   const int* __restrict__ tgt,
                                                   const float* __restrict__ Wq,
                                                   const float* __restrict__ bq,
                                                   const float* __restrict__ Wk,
                                                   const float* __restrict__ bk,
                                                   const float* __restrict__ We,
                                                   const float* __restrict__ Wv,
                                                   const float* __restrict__ bv)
{
    __shared__ float sa[4][16];     // coefA per layer (t fixed per block)
    __shared__ float sp[4][12];     // coefP[0..4], coefQ at [5..9]

    int tid = threadIdx.x;
    int wid = tid >> 5, lane = tid & 31;
    int idx = blockIdx.x * 256 + tid;   // 0 .. T*E-1
    int t = (blockIdx.x * 256) >> 16;   // constant per block (256 | E)

    if (wid < 4) {
        // coefA for tl = t*4 + wid
        int tl = t * LL + wid;
        const float* wq0 = Wq + (size_t)tl * 2 * HH;
        const float* wq1 = wq0 + HH;
        const float* bqp = bq + (size_t)tl * HH;
        float q0a = wq0[lane], q0b = wq0[lane + 32];
        float q1a = wq1[lane], q1b = wq1[lane + 32];
        float bba = bqp[lane], bbb = bqp[lane + 32];

        const float* Xs[5];
        Xs[0] = Wk + (size_t)tl * 2 * HH;
        Xs[1] = Xs[0] + HH;
        Xs[2] = We + (size_t)tl * 2 * HH;
        Xs[3] = Xs[2] + HH;
        Xs[4] = bk + (size_t)tl * HH;

        float pa[15];
#pragma unroll
        for (int k = 0; k < 5; k++) {
            float xa = Xs[k][lane], xb = Xs[k][lane + 32];
            pa[3*k + 0] = q0a * xa + q0b * xb;
            pa[3*k + 1] = q1a * xa + q1b * xb;
            pa[3*k + 2] = bba * xa + bbb * xb;
        }
#pragma unroll
        for (int off = 16; off > 0; off >>= 1)
#pragma unroll
            for (int i = 0; i < 15; i++)
                pa[i] += __shfl_down_sync(0xffffffffu, pa[i], off);
        if (lane == 0) {
#pragma unroll
            for (int i = 0; i < 15; i++) sa[wid][i] = pa[i];
            sa[wid][15] = 0.0f;
        }
    } else {
        // coefP/Q for tl = t*4 + (wid-4)
        int lw = wid - 4;
        int tl = t * LL + lw;
        const float* Ys[5];
        Ys[0] = Wv + (size_t)tl * 2 * HH;
        Ys[1] = Ys[0] + HH;
        Ys[2] = We + (size_t)tl * 2 * HH;
        Ys[3] = Ys[2] + HH;
        Ys[4] = bv + (size_t)tl * HH;

        float ph[10];
#pragma unroll
        for (int k = 0; k < 5; k++) {
            ph[k]     = Ys[k][lane];            // low half (h<32)
            ph[5 + k] = Ys[k][lane + 32];       // high half
        }
#pragma unroll
        for (int off = 16; off > 0; off >>= 1)
#pragma unroll
            for (int i = 0; i < 10; i++)
                ph[i] += __shfl_down_sync(0xffffffffu, ph[i], off);
        if (lane == 0)
#pragma unroll
            for (int i = 0; i < 10; i++) sp[lw][i] = ph[i];
    }
    __syncthreads();

    int s = src[idx];
    int g = tgt[idx];
    float xs0 = x[2 * s], xs1 = x[2 * s + 1];
    float ea0 = ea[2 * idx], ea1 = ea[2 * idx + 1];
    int tn = t * NN + g;
    float xt0 = x[2 * tn], xt1 = x[2 * tn + 1];

#pragma unroll
    for (int l = 0; l < LL; l++) {
        const float* c = sa[l];
        float A0 = fmaf(c[0],  xt0, fmaf(c[1],  xt1, c[2]));
        float A1 = fmaf(c[3],  xt0, fmaf(c[4],  xt1, c[5]));
        float A2 = fmaf(c[6],  xt0, fmaf(c[7],  xt1, c[8]));
        float A3 = fmaf(c[9],  xt0, fmaf(c[10], xt1, c[11]));
        float A4 = fmaf(c[12], xt0, fmaf(c[13], xt1, c[14]));
        float alpha = (A0 * xs0 + A1 * xs1 + A2 * ea0 + A3 * ea1 + A4) * 0.125f;
        float w = expf(alpha);   // |alpha| is O(1): shift-free softmax is safe

        const float* hh = sp[l];
        float p = fmaf(hh[0], xs0, fmaf(hh[1], xs1, fmaf(hh[2], ea0, fmaf(hh[3], ea1, hh[4]))));
        float q = fmaf(hh[5], xs0, fmaf(hh[6], xs1, fmaf(hh[7], ea0, fmaf(hh[8], ea1, hh[9]))));

        float* sm = &g_sums[((t * LL + l) * NN + g) * 8];
        asm volatile("red.global.add.v4.f32 [%0], {%1, %2, %3, %4};"
                     :: "l"(sm), "f"(w * p), "f"(w * q), "f"(w), "f"(0.0f)
                     : "memory");
    }
}

// ---------------- K2: node pass — normalize, add skip terms, restore zeros ----------------
__global__ void __launch_bounds__(256) node_kernel(const float* __restrict__ x,
                                                   const float* __restrict__ Wsk,
                                                   const float* __restrict__ bsk)
{
    __shared__ float h[8];   // skip coefs: [0..2]={Wsk0,Wsk1,bsk} low half, [3..5]=high half

    int tid = threadIdx.x;
    int idx = blockIdx.x * 256 + tid;   // 0 .. T*L*N-1
    int tl = (blockIdx.x * 256) >> 11;  // constant per block (256 | N)
    int t = tl >> 2;
    int l = tl & 3;
    int n = idx & (NN - 1);

    if (tid < 32) {
        int lane = tid;
        const float* Ys[3];
        Ys[0] = Wsk + (size_t)tl * 2 * HH;
        Ys[1] = Ys[0] + HH;
        Ys[2] = bsk + (size_t)tl * HH;

        float ph[6];
#pragma unroll
        for (int k = 0; k < 3; k++) {
            ph[k]     = Ys[k][lane];
            ph[3 + k] = Ys[k][lane + 32];
        }
#pragma unroll
        for (int off = 16; off > 0; off >>= 1)
#pragma unroll
            for (int i = 0; i < 6; i++)
                ph[i] += __shfl_down_sync(0xffffffffu, ph[i], off);
        if (lane == 0)
#pragma unroll
            for (int i = 0; i < 6; i++) h[i] = ph[i];
    }
    __syncthreads();

    float* smp = &g_sums[idx * 8];
    float4 v = *reinterpret_cast<float4*>(smp);   // {sum_wp, sum_wq, sum_w, 0}

    // restore zeros for next replay (only first 16B are ever written)
    *reinterpret_cast<float4*>(smp) = make_float4(0.f, 0.f, 0.f, 0.f);

    float inv = 1.0f / (v.z + 1e-16f);

    int tn = t * NN + n;
    float xt0 = x[2 * tn], xt1 = x[2 * tn + 1];

    float P = v.x * inv + fmaf(h[0], xt0, fmaf(h[1], xt1, h[2]));
    float Q = v.y * inv + fmaf(h[3], xt0, fmaf(h[4], xt1, h[5]));

    int vo = t * (2 * LL * NN) + 2 * (l * NN + n);
    g_val[vo]     = P;
    g_val[vo + 1] = Q;
}

// ---------------- K3: GEMV — unchanged from R5 (8 warps x 2 rows, __ldcs) ----------------
__global__ void __launch_bounds__(256) gemv_kernel(const float* __restrict__ Wfc,
                                                   const float* __restrict__ bfc,
                                                   float* __restrict__ out)
{
    const int t = blockIdx.y;
    const int rowBase = blockIdx.x * 16;
    __shared__ float4 sv[1024];                    // 16 KB chunk of val

    int tid = threadIdx.x;
    int lane = tid & 31;
    int w = tid >> 5;
    int r0 = rowBase + w;
    int r1 = rowBase + 8 + w;

    const float4* val4 = reinterpret_cast<const float4*>(g_val + t * (2 * LL * NN));
    const float4* W0 = reinterpret_cast<const float4*>(Wfc + ((size_t)(t * 4096 + r0)) * 16384);
    const float4* W1 = reinterpret_cast<const float4*>(Wfc + ((size_t)(t * 4096 + r1)) * 16384);

    float4 a0 = make_float4(0.f, 0.f, 0.f, 0.f);
    float4 a1 = make_float4(0.f, 0.f, 0.f, 0.f);

#pragma unroll
    for (int c = 0; c < 4; c++) {
        for (int j = tid; j < 1024; j += 256)
            sv[j] = val4[c * 1024 + j];
        __syncthreads();

        const int base = c * 1024;
#pragma unroll 8
        for (int j = lane; j < 1024; j += 32) {
            float4 v  = sv[j];
            float4 w0 = __ldcs(&W0[base + j]);   // streaming: no-reuse 1GB scan
            float4 w1 = __ldcs(&W1[base + j]);
            a0.x = fmaf(w0.x, v.x, a0.x);
            a0.y = fmaf(w0.y, v.y, a0.y);
            a0.z = fmaf(w0.z, v.z, a0.z);
            a0.w = fmaf(w0.w, v.w, a0.w);
            a1.x = fmaf(w1.x, v.x, a1.x);
            a1.y = fmaf(w1.y, v.y, a1.y);
            a1.z = fmaf(w1.z, v.z, a1.z);
            a1.w = fmaf(w1.w, v.w, a1.w);
        }
        __syncthreads();
    }

    float s0 = (a0.x + a0.y) + (a0.z + a0.w);
    float s1 = (a1.x + a1.y) + (a1.z + a1.w);
#pragma unroll
    for (int off = 16; off > 0; off >>= 1) {
        s0 += __shfl_down_sync(0xffffffffu, s0, off);
        s1 += __shfl_down_sync(0xffffffffu, s1, off);
    }
    if (lane == 0) {
        out[t * 4096 + r0] = s0 + bfc[t * 4096 + r0];
        out[t * 4096 + r1] = s1 + bfc[t * 4096 + r1];
    }
}

// ---------------- launch: 3 kernels, single stream ----------------
extern "C" void kernel_launch(void* const* d_in, const int* in_sizes, int n_in,
                              void* d_out, int out_size)
{
    const float* x    = (const float*)d_in[0];
    const float* ea   = (const float*)d_in[1];
    const int*   src  = (const int*)  d_in[2];
    const int*   tgt  = (const int*)  d_in[3];
    const float* Wq   = (const float*)d_in[4];
    const float* bq   = (const float*)d_in[5];
    const float* Wk   = (const float*)d_in[6];
    const float* bk   = (const float*)d_in[7];
    const float* Wv   = (const float*)d_in[8];
    const float* bv   = (const float*)d_in[9];
    const float* We   = (const float*)d_in[10];
    const float* Wsk  = (const float*)d_in[11];
    const float* bsk  = (const float*)d_in[12];
    const float* Wfc  = (const float*)d_in[13];
    const float* bfc  = (const float*)d_in[14];
    float* out = (float*)d_out;

    edge_kernel<<<(TT * EE) / 256, 256>>>(x, ea, src, tgt, Wq, bq, Wk, bk, We, Wv, bv);
    node_kernel<<<(TL * NN) / 256, 256>>>(x, Wsk, bsk);
    gemv_kernel<<<dim3(256, TT), 256>>>(Wfc, bfc, out);
}

// round 13
// speedup vs baseline: 1.3111x; 1.0070x over previous
#include <cuda_runtime.h>

// Problem constants: T=4, L=4, N=2048, E=65536, H=64, C=2
#define TT 4
#define LL 4
#define NN 2048
#define EE 65536
#define HH 64
#define TL (TT*LL)

// ---------------- device scratch ----------------
// stride-8 rows (32B): [0]=sum(w*p), [1]=sum(w*q), [2]=sum(w), [3]=0 (v4 pad), [4..7] unused.
// One 32B LTS sector per (t,l,n) row -> single red.v4 per edge-layer, no sector sharing.
// Zero at module load; node_kernel restores zeros every call.
__device__ float g_sums[TL * NN * 8];
__device__ float g_val[TT * 2 * LL * NN];   // [T][2*L*N]

// ---------------- K1: edge pass — folded coefs, ONE red.v4 per edge-layer ----------------
// Also prefetches the head of every Wfc row into L2 (DRAM is idle during this pass;
// the GEMV then sources those bytes from L2).
__global__ void __launch_bounds__(256) edge_kernel(const float* __restrict__ x,
                                                   const float* __restrict__ ea,
                                                   const int* __restrict__ src,
                                                   const int* __restrict__ tgt,
                                                   const float* __restrict__ Wq,
                                                   const float* __restrict__ bq,
                                                   const float* __restrict__ Wk,
                                                   const float* __restrict__ bk,
                                                   const float* __restrict__ We,
                                                   const float* __restrict__ Wv,
                                                   const float* __restrict__ bv,
                                                   const float* __restrict__ Wfc)
{
    __shared__ float sa[4][16];     // coefA per layer (t fixed per block)
    __shared__ float sp[4][12];     // coefP[0..4], coefQ at [5..9]

    int tid = threadIdx.x;
    int wid = tid >> 5, lane = tid & 31;
    int idx = blockIdx.x * 256 + tid;   // 0 .. T*E-1
    int t = (blockIdx.x * 256) >> 16;   // constant per block (256 | E)

    if (wid < 4) {
        // coefA for tl = t*4 + wid
        int tl = t * LL + wid;
        const float* wq0 = Wq + (size_t)tl * 2 * HH;
        const float* wq1 = wq0 + HH;
        const float* bqp = bq + (size_t)tl * HH;
        float q0a = wq0[lane], q0b = wq0[lane + 32];
        float q1a = wq1[lane], q1b = wq1[lane + 32];
        float bba = bqp[lane], bbb = bqp[lane + 32];

        const float* Xs[5];
        Xs[0] = Wk + (size_t)tl * 2 * HH;
        Xs[1] = Xs[0] + HH;
        Xs[2] = We + (size_t)tl * 2 * HH;
        Xs[3] = Xs[2] + HH;
        Xs[4] = bk + (size_t)tl * HH;

        float pa[15];
#pragma unroll
        for (int k = 0; k < 5; k++) {
            float xa = Xs[k][lane], xb = Xs[k][lane + 32];
            pa[3*k + 0] = q0a * xa + q0b * xb;
            pa[3*k + 1] = q1a * xa + q1b * xb;
            pa[3*k + 2] = bba * xa + bbb * xb;
        }
#pragma unroll
        for (int off = 16; off > 0; off >>= 1)
#pragma unroll
            for (int i = 0; i < 15; i++)
                pa[i] += __shfl_down_sync(0xffffffffu, pa[i], off);
        if (lane == 0) {
#pragma unroll
            for (int i = 0; i < 15; i++) sa[wid][i] = pa[i];
            sa[wid][15] = 0.0f;
        }
    } else {
        // coefP/Q for tl = t*4 + (wid-4)
        int lw = wid - 4;
        int tl = t * LL + lw;
        const float* Ys[5];
        Ys[0] = Wv + (size_t)tl * 2 * HH;
        Ys[1] = Ys[0] + HH;
        Ys[2] = We + (size_t)tl * 2 * HH;
        Ys[3] = Ys[2] + HH;
        Ys[4] = bv + (size_t)tl * HH;

        float ph[10];
#pragma unroll
        for (int k = 0; k < 5; k++) {
            ph[k]     = Ys[k][lane];            // low half (h<32)
            ph[5 + k] = Ys[k][lane + 32];       // high half
        }
#pragma unroll
        for (int off = 16; off > 0; off >>= 1)
#pragma unroll
            for (int i = 0; i < 10; i++)
                ph[i] += __shfl_down_sync(0xffffffffu, ph[i], off);
        if (lane == 0)
#pragma unroll
            for (int i = 0; i < 10; i++) sp[lw][i] = ph[i];
    }
    __syncthreads();

    // Kick off the Wfc L2 prefetch FIRST (fire-and-forget; fills DRAM idle time).
    // First 6KB of each of the 16384 rows = 48 x 128B sectors/row = 786432 sectors,
    // 3 per thread across 262144 threads.
    {
        int gtid = blockIdx.x * 256 + tid;
#pragma unroll
        for (int k = 0; k < 3; k++) {
            int sec = gtid * 3 + k;
            int row = sec / 48;
            int s   = sec - row * 48;
            const char* p = (const char*)Wfc + (size_t)row * 65536 + (size_t)s * 128;
            asm volatile("prefetch.global.L2 [%0];" :: "l"(p));
        }
    }

    int s = src[idx];
    int g = tgt[idx];
    float xs0 = x[2 * s], xs1 = x[2 * s + 1];
    float ea0 = ea[2 * idx], ea1 = ea[2 * idx + 1];
    int tn = t * NN + g;
    float xt0 = x[2 * tn], xt1 = x[2 * tn + 1];

#pragma unroll
    for (int l = 0; l < LL; l++) {
        const float* c = sa[l];
        float A0 = fmaf(c[0],  xt0, fmaf(c[1],  xt1, c[2]));
        float A1 = fmaf(c[3],  xt0, fmaf(c[4],  xt1, c[5]));
        float A2 = fmaf(c[6],  xt0, fmaf(c[7],  xt1, c[8]));
        float A3 = fmaf(c[9],  xt0, fmaf(c[10], xt1, c[11]));
        float A4 = fmaf(c[12], xt0, fmaf(c[13], xt1, c[14]));
        float alpha = (A0 * xs0 + A1 * xs1 + A2 * ea0 + A3 * ea1 + A4) * 0.125f;
        float w = expf(alpha);   // |alpha| is O(1): shift-free softmax is safe

        const float* hh = sp[l];
        float p = fmaf(hh[0], xs0, fmaf(hh[1], xs1, fmaf(hh[2], ea0, fmaf(hh[3], ea1, hh[4]))));
        float q = fmaf(hh[5], xs0, fmaf(hh[6], xs1, fmaf(hh[7], ea0, fmaf(hh[8], ea1, hh[9]))));

        float* sm = &g_sums[((t * LL + l) * NN + g) * 8];
        asm volatile("red.global.add.v4.f32 [%0], {%1, %2, %3, %4};"
                     :: "l"(sm), "f"(w * p), "f"(w * q), "f"(w), "f"(0.0f)
                     : "memory");
    }
}

// ---------------- K2: node pass — normalize, add skip terms, restore zeros ----------------
__global__ void __launch_bounds__(256) node_kernel(const float* __restrict__ x,
                                                   const float* __restrict__ Wsk,
                                                   const float* __restrict__ bsk)
{
    __shared__ float h[8];   // skip coefs: [0..2]={Wsk0,Wsk1,bsk} low half, [3..5]=high half

    int tid = threadIdx.x;
    int idx = blockIdx.x * 256 + tid;   // 0 .. T*L*N-1
    int tl = (blockIdx.x * 256) >> 11;  // constant per block (256 | N)
    int t = tl >> 2;
    int l = tl & 3;
    int n = idx & (NN - 1);

    if (tid < 32) {
        int lane = tid;
        const float* Ys[3];
        Ys[0] = Wsk + (size_t)tl * 2 * HH;
        Ys[1] = Ys[0] + HH;
        Ys[2] = bsk + (size_t)tl * HH;

        float ph[6];
#pragma unroll
        for (int k = 0; k < 3; k++) {
            ph[k]     = Ys[k][lane];
            ph[3 + k] = Ys[k][lane + 32];
        }
#pragma unroll
        for (int off = 16; off > 0; off >>= 1)
#pragma unroll
            for (int i = 0; i < 6; i++)
                ph[i] += __shfl_down_sync(0xffffffffu, ph[i], off);
        if (lane == 0)
#pragma unroll
            for (int i = 0; i < 6; i++) h[i] = ph[i];
    }
    __syncthreads();

    float* smp = &g_sums[idx * 8];
    float4 v = *reinterpret_cast<float4*>(smp);   // {sum_wp, sum_wq, sum_w, 0}

    // restore zeros for next replay (only first 16B are ever written)
    *reinterpret_cast<float4*>(smp) = make_float4(0.f, 0.f, 0.f, 0.f);

    float inv = 1.0f / (v.z + 1e-16f);

    int tn = t * NN + n;
    float xt0 = x[2 * tn], xt1 = x[2 * tn + 1];

    float P = v.x * inv + fmaf(h[0], xt0, fmaf(h[1], xt1, h[2]));
    float Q = v.y * inv + fmaf(h[3], xt0, fmaf(h[4], xt1, h[5]));

    int vo = t * (2 * LL * NN) + 2 * (l * NN + n);
    g_val[vo]     = P;
    g_val[vo + 1] = Q;
}

// ---------------- K3: GEMV — unchanged (8 warps x 2 rows, __ldcs) ----------------
__global__ void __launch_bounds__(256) gemv_kernel(const float* __restrict__ Wfc,
                                                   const float* __restrict__ bfc,
                                                   float* __restrict__ out)
{
    const int t = blockIdx.y;
    const int rowBase = blockIdx.x * 16;
    __shared__ float4 sv[1024];                    // 16 KB chunk of val

    int tid = threadIdx.x;
    int lane = tid & 31;
    int w = tid >> 5;
    int r0 = rowBase + w;
    int r1 = rowBase + 8 + w;

    const float4* val4 = reinterpret_cast<const float4*>(g_val + t * (2 * LL * NN));
    const float4* W0 = reinterpret_cast<const float4*>(Wfc + ((size_t)(t * 4096 + r0)) * 16384);
    const float4* W1 = reinterpret_cast<const float4*>(Wfc + ((size_t)(t * 4096 + r1)) * 16384);

    float4 a0 = make_float4(0.f, 0.f, 0.f, 0.f);
    float4 a1 = make_float4(0.f, 0.f, 0.f, 0.f);

#pragma unroll
    for (int c = 0; c < 4; c++) {
        for (int j = tid; j < 1024; j += 256)
            sv[j] = val4[c * 1024 + j];
        __syncthreads();

        const int base = c * 1024;
#pragma unroll 8
        for (int j = lane; j < 1024; j += 32) {
            float4 v  = sv[j];
            float4 w0 = __ldcs(&W0[base + j]);   // streaming: no-reuse 1GB scan
            float4 w1 = __ldcs(&W1[base + j]);
            a0.x = fmaf(w0.x, v.x, a0.x);
            a0.y = fmaf(w0.y, v.y, a0.y);
            a0.z = fmaf(w0.z, v.z, a0.z);
            a0.w = fmaf(w0.w, v.w, a0.w);
            a1.x = fmaf(w1.x, v.x, a1.x);
            a1.y = fmaf(w1.y, v.y, a1.y);
            a1.z = fmaf(w1.z, v.z, a1.z);
            a1.w = fmaf(w1.w, v.w, a1.w);
        }
        __syncthreads();
    }

    float s0 = (a0.x + a0.y) + (a0.z + a0.w);
    float s1 = (a1.x + a1.y) + (a1.z + a1.w);
#pragma unroll
    for (int off = 16; off > 0; off >>= 1) {
        s0 += __shfl_down_sync(0xffffffffu, s0, off);
        s1 += __shfl_down_sync(0xffffffffu, s1, off);
    }
    if (lane == 0) {
        out[t * 4096 + r0] = s0 + bfc[t * 4096 + r0];
        out[t * 4096 + r1] = s1 + bfc[t * 4096 + r1];
    }
}

// ---------------- launch: 3 kernels, single stream ----------------
extern "C" void kernel_launch(void* const* d_in, const int* in_sizes, int n_in,
                              void* d_out, int out_size)
{
    const float* x    = (const float*)d_in[0];
    const float* ea   = (const float*)d_in[1];
    const int*   src  = (const int*)  d_in[2];
    const int*   tgt  = (const int*)  d_in[3];
    const float* Wq   = (const float*)d_in[4];
    const float* bq   = (const float*)d_in[5];
    const float* Wk   = (const float*)d_in[6];
    const float* bk   = (const float*)d_in[7];
    const float* Wv   = (const float*)d_in[8];
    const float* bv   = (const float*)d_in[9];
    const float* We   = (const float*)d_in[10];
    const float* Wsk  = (const float*)d_in[11];
    const float* bsk  = (const float*)d_in[12];
    const float* Wfc  = (const float*)d_in[13];
    const float* bfc  = (const float*)d_in[14];
    float* out = (float*)d_out;

    edge_kernel<<<(TT * EE) / 256, 256>>>(x, ea, src, tgt, Wq, bq, Wk, bk, We, Wv, bv, Wfc);
    node_kernel<<<(TL * NN) / 256, 256>>>(x, Wsk, bsk);
    gemv_kernel<<<dim3(256, TT), 256>>>(Wfc, bfc, out);
}

// round 14
// speedup vs baseline: 1.3478x; 1.0280x over previous
#include <cuda_runtime.h>

// Problem constants: T=4, L=4, N=2048, E=65536, H=64, C=2
#define TT 4
#define LL 4
#define NN 2048
#define EE 65536
#define HH 64
#define TL (TT*LL)

// ---------------- device scratch ----------------
// stride-8 rows (32B): [0]=sum(w*p), [1]=sum(w*q), [2]=sum(w), [3]=0 (v4 pad), [4..7] unused.
// One 32B LTS sector per (t,l,n) row -> single red.v4 per edge-layer, no sector sharing.
// Zero at module load; node_kernel restores zeros every call.
__device__ float g_sums[TL * NN * 8];
__device__ float g_val[TT * 2 * LL * NN];   // [T][2*L*N]

// ---------------- K1: edge pass — folded coefs, ONE red.v4 per edge-layer ----------------
// Prefetches the first 4KB of every Wfc row into L2 (64 MB total — sized to the
// DRAM-idle budget of this pass so the kernel is not extended much past its
// 12.8us compute floor; R13 showed prefetch drains at ~4.7 TB/s).
__global__ void __launch_bounds__(256) edge_kernel(const float* __restrict__ x,
                                                   const float* __restrict__ ea,
                                                   const int* __restrict__ src,
                                                   const int* __restrict__ tgt,
                                                   const float* __restrict__ Wq,
                                                   const float* __restrict__ bq,
                                                   const float* __restrict__ Wk,
                                                   const float* __restrict__ bk,
                                                   const float* __restrict__ We,
                                                   const float* __restrict__ Wv,
                                                   const float* __restrict__ bv,
                                                   const float* __restrict__ Wfc)
{
    __shared__ float sa[4][16];     // coefA per layer (t fixed per block)
    __shared__ float sp[4][12];     // coefP[0..4], coefQ at [5..9]

    int tid = threadIdx.x;
    int wid = tid >> 5, lane = tid & 31;
    int idx = blockIdx.x * 256 + tid;   // 0 .. T*E-1
    int t = (blockIdx.x * 256) >> 16;   // constant per block (256 | E)

    if (wid < 4) {
        // coefA for tl = t*4 + wid
        int tl = t * LL + wid;
        const float* wq0 = Wq + (size_t)tl * 2 * HH;
        const float* wq1 = wq0 + HH;
        const float* bqp = bq + (size_t)tl * HH;
        float q0a = wq0[lane], q0b = wq0[lane + 32];
        float q1a = wq1[lane], q1b = wq1[lane + 32];
        float bba = bqp[lane], bbb = bqp[lane + 32];

        const float* Xs[5];
        Xs[0] = Wk + (size_t)tl * 2 * HH;
        Xs[1] = Xs[0] + HH;
        Xs[2] = We + (size_t)tl * 2 * HH;
        Xs[3] = Xs[2] + HH;
        Xs[4] = bk + (size_t)tl * HH;

        float pa[15];
#pragma unroll
        for (int k = 0; k < 5; k++) {
            float xa = Xs[k][lane], xb = Xs[k][lane + 32];
            pa[3*k + 0] = q0a * xa + q0b * xb;
            pa[3*k + 1] = q1a * xa + q1b * xb;
            pa[3*k + 2] = bba * xa + bbb * xb;
        }
#pragma unroll
        for (int off = 16; off > 0; off >>= 1)
#pragma unroll
            for (int i = 0; i < 15; i++)
                pa[i] += __shfl_down_sync(0xffffffffu, pa[i], off);
        if (lane == 0) {
#pragma unroll
            for (int i = 0; i < 15; i++) sa[wid][i] = pa[i];
            sa[wid][15] = 0.0f;
        }
    } else {
        // coefP/Q for tl = t*4 + (wid-4)
        int lw = wid - 4;
        int tl = t * LL + lw;
        const float* Ys[5];
        Ys[0] = Wv + (size_t)tl * 2 * HH;
        Ys[1] = Ys[0] + HH;
        Ys[2] = We + (size_t)tl * 2 * HH;
        Ys[3] = Ys[2] + HH;
        Ys[4] = bv + (size_t)tl * HH;

        float ph[10];
#pragma unroll
        for (int k = 0; k < 5; k++) {
            ph[k]     = Ys[k][lane];            // low half (h<32)
            ph[5 + k] = Ys[k][lane + 32];       // high half
        }
#pragma unroll
        for (int off = 16; off > 0; off >>= 1)
#pragma unroll
            for (int i = 0; i < 10; i++)
                ph[i] += __shfl_down_sync(0xffffffffu, ph[i], off);
        if (lane == 0)
#pragma unroll
            for (int i = 0; i < 10; i++) sp[lw][i] = ph[i];
    }
    __syncthreads();

    // Wfc L2 prefetch: first 4KB of each row = 32 x 128B sectors/row,
    // 16384 rows -> 524288 sectors, 2 per thread across 262144 threads.
    {
        int gtid = blockIdx.x * 256 + tid;
#pragma unroll
        for (int k = 0; k < 2; k++) {
            int sec = gtid * 2 + k;
            int row = sec >> 5;
            int s   = sec & 31;
            const char* p = (const char*)Wfc + (size_t)row * 65536 + (size_t)s * 128;
            asm volatile("prefetch.global.L2 [%0];" :: "l"(p));
        }
    }

    int s = src[idx];
    int g = tgt[idx];
    float xs0 = x[2 * s], xs1 = x[2 * s + 1];
    float ea0 = ea[2 * idx], ea1 = ea[2 * idx + 1];
    int tn = t * NN + g;
    float xt0 = x[2 * tn], xt1 = x[2 * tn + 1];

#pragma unroll
    for (int l = 0; l < LL; l++) {
        const float* c = sa[l];
        float A0 = fmaf(c[0],  xt0, fmaf(c[1],  xt1, c[2]));
        float A1 = fmaf(c[3],  xt0, fmaf(c[4],  xt1, c[5]));
        float A2 = fmaf(c[6],  xt0, fmaf(c[7],  xt1, c[8]));
        float A3 = fmaf(c[9],  xt0, fmaf(c[10], xt1, c[11]));
        float A4 = fmaf(c[12], xt0, fmaf(c[13], xt1, c[14]));
        float alpha = (A0 * xs0 + A1 * xs1 + A2 * ea0 + A3 * ea1 + A4) * 0.125f;
        float w = expf(alpha);   // |alpha| is O(1): shift-free softmax is safe

        const float* hh = sp[l];
        float p = fmaf(hh[0], xs0, fmaf(hh[1], xs1, fmaf(hh[2], ea0, fmaf(hh[3], ea1, hh[4]))));
        float q = fmaf(hh[5], xs0, fmaf(hh[6], xs1, fmaf(hh[7], ea0, fmaf(hh[8], ea1, hh[9]))));

        float* sm = &g_sums[((t * LL + l) * NN + g) * 8];
        asm volatile("red.global.add.v4.f32 [%0], {%1, %2, %3, %4};"
                     :: "l"(sm), "f"(w * p), "f"(w * q), "f"(w), "f"(0.0f)
                     : "memory");
    }
}

// ---------------- K2: node pass — normalize, add skip, restore zeros, prefetch more Wfc ----------------
__global__ void __launch_bounds__(256) node_kernel(const float* __restrict__ x,
                                                   const float* __restrict__ Wsk,
                                                   const float* __restrict__ bsk,
                                                   const float* __restrict__ Wfc)
{
    __shared__ float h[8];   // skip coefs: [0..2]={Wsk0,Wsk1,bsk} low half, [3..5]=high half

    int tid = threadIdx.x;
    int idx = blockIdx.x * 256 + tid;   // 0 .. T*L*N-1
    int tl = (blockIdx.x * 256) >> 11;  // constant per block (256 | N)
    int t = tl >> 2;
    int l = tl & 3;
    int n = idx & (NN - 1);

    if (tid < 32) {
        int lane = tid;
        const float* Ys[3];
        Ys[0] = Wsk + (size_t)tl * 2 * HH;
        Ys[1] = Ys[0] + HH;
        Ys[2] = bsk + (size_t)tl * HH;

        float ph[6];
#pragma unroll
        for (int k = 0; k < 3; k++) {
            ph[k]     = Ys[k][lane];
            ph[3 + k] = Ys[k][lane + 32];
        }
#pragma unroll
        for (int off = 16; off > 0; off >>= 1)
#pragma unroll
            for (int i = 0; i < 6; i++)
                ph[i] += __shfl_down_sync(0xffffffffu, ph[i], off);
        if (lane == 0)
#pragma unroll
            for (int i = 0; i < 6; i++) h[i] = ph[i];
    }
    __syncthreads();

    // Continue the Wfc prefetch: next 1KB of each row (bytes 4096..5119) =
    // 8 sectors/row x 16384 rows = 131072 sectors, 4 per thread across 32768 threads.
    {
#pragma unroll
        for (int k = 0; k < 4; k++) {
            int sec = idx * 4 + k;
            int row = sec >> 3;
            int s   = 32 + (sec & 7);
            const char* p = (const char*)Wfc + (size_t)row * 65536 + (size_t)s * 128;
            asm volatile("prefetch.global.L2 [%0];" :: "l"(p));
        }
    }

    float* smp = &g_sums[idx * 8];
    float4 v = *reinterpret_cast<float4*>(smp);   // {sum_wp, sum_wq, sum_w, 0}

    // restore zeros for next replay (only first 16B are ever written)
    *reinterpret_cast<float4*>(smp) = make_float4(0.f, 0.f, 0.f, 0.f);

    float inv = 1.0f / (v.z + 1e-16f);

    int tn = t * NN + n;
    float xt0 = x[2 * tn], xt1 = x[2 * tn + 1];

    float P = v.x * inv + fmaf(h[0], xt0, fmaf(h[1], xt1, h[2]));
    float Q = v.y * inv + fmaf(h[3], xt0, fmaf(h[4], xt1, h[5]));

    int vo = t * (2 * LL * NN) + 2 * (l * NN + n);
    g_val[vo]     = P;
    g_val[vo + 1] = Q;
}

// ---------------- K3: GEMV — unchanged (8 warps x 2 rows, __ldcs) ----------------
__global__ void __launch_bounds__(256) gemv_kernel(const float* __restrict__ Wfc,
                                                   const float* __restrict__ bfc,
                                                   float* __restrict__ out)
{
    const int t = blockIdx.y;
    const int rowBase = blockIdx.x * 16;
    __shared__ float4 sv[1024];                    // 16 KB chunk of val

    int tid = threadIdx.x;
    int lane = tid & 31;
    int w = tid >> 5;
    int r0 = rowBase + w;
    int r1 = rowBase + 8 + w;

    const float4* val4 = reinterpret_cast<const float4*>(g_val + t * (2 * LL * NN));
    const float4* W0 = reinterpret_cast<const float4*>(Wfc + ((size_t)(t * 4096 + r0)) * 16384);
    const float4* W1 = reinterpret_cast<const float4*>(Wfc + ((size_t)(t * 4096 + r1)) * 16384);

    float4 a0 = make_float4(0.f, 0.f, 0.f, 0.f);
    float4 a1 = make_float4(0.f, 0.f, 0.f, 0.f);

#pragma unroll
    for (int c = 0; c < 4; c++) {
        for (int j = tid; j < 1024; j += 256)
            sv[j] = val4[c * 1024 + j];
        __syncthreads();

        const int base = c * 1024;
#pragma unroll 8
        for (int j = lane; j < 1024; j += 32) {
            float4 v  = sv[j];
            float4 w0 = __ldcs(&W0[base + j]);   // streaming: no-reuse 1GB scan
            float4 w1 = __ldcs(&W1[base + j]);
            a0.x = fmaf(w0.x, v.x, a0.x);
            a0.y = fmaf(w0.y, v.y, a0.y);
            a0.z = fmaf(w0.z, v.z, a0.z);
            a0.w = fmaf(w0.w, v.w, a0.w);
            a1.x = fmaf(w1.x, v.x, a1.x);
            a1.y = fmaf(w1.y, v.y, a1.y);
            a1.z = fmaf(w1.z, v.z, a1.z);
            a1.w = fmaf(w1.w, v.w, a1.w);
        }
        __syncthreads();
    }

    float s0 = (a0.x + a0.y) + (a0.z + a0.w);
    float s1 = (a1.x + a1.y) + (a1.z + a1.w);
#pragma unroll
    for (int off = 16; off > 0; off >>= 1) {
        s0 += __shfl_down_sync(0xffffffffu, s0, off);
        s1 += __shfl_down_sync(0xffffffffu, s1, off);
    }
    if (lane == 0) {
        out[t * 4096 + r0] = s0 + bfc[t * 4096 + r0];
        out[t * 4096 + r1] = s1 + bfc[t * 4096 + r1];
    }
}

// ---------------- launch: 3 kernels, single stream ----------------
extern "C" void kernel_launch(void* const* d_in, const int* in_sizes, int n_in,
                              void* d_out, int out_size)
{
    const float* x    = (const float*)d_in[0];
    const float* ea   = (const float*)d_in[1];
    const int*   src  = (const int*)  d_in[2];
    const int*   tgt  = (const int*)  d_in[3];
    const float* Wq   = (const float*)d_in[4];
    const float* bq   = (const float*)d_in[5];
    const float* Wk   = (const float*)d_in[6];
    const float* bk   = (const float*)d_in[7];
    const float* Wv   = (const float*)d_in[8];
    const float* bv   = (const float*)d_in[9];
    const float* We   = (const float*)d_in[10];
    const float* Wsk  = (const float*)d_in[11];
    const float* bsk  = (const float*)d_in[12];
    const float* Wfc  = (const float*)d_in[13];
    const float* bfc  = (const float*)d_in[14];
    float* out = (float*)d_out;

    edge_kernel<<<(TT * EE) / 256, 256>>>(x, ea, src, tgt, Wq, bq, Wk, bk, We, Wv, bv, Wfc);
    node_kernel<<<(TL * NN) / 256, 256>>>(x, Wsk, bsk, Wfc);
    gemv_kernel<<<dim3(256, TT), 256>>>(Wfc, bfc, out);
}

// round 15
// speedup vs baseline: 1.3578x; 1.0074x over previous
#include <cuda_runtime.h>

// Problem constants: T=4, L=4, N=2048, E=65536, H=64, C=2
#define TT 4
#define LL 4
#define NN 2048
#define EE 65536
#define HH 64
#define TL (TT*LL)

// ---------------- device scratch ----------------
// stride-8 rows (32B): [0]=sum(w*p), [1]=sum(w*q), [2]=sum(w), [3]=0 (v4 pad), [4..7] unused.
// One 32B LTS sector per (t,l,n) row -> single red.v4 per edge-layer, no sector sharing.
// Zero at module load; node_kernel restores zeros every call.
__device__ float g_sums[TL * NN * 8];
__device__ float g_val[TT * 2 * LL * NN];   // [T][2*L*N]

// ---------------- K1: edge pass — folded coefs, ONE red.v4 per edge-layer ----------------
// Prefetches the first 4KB of every Wfc row into L2 (64 MB), issued at kernel TOP so
// the drain overlaps the whole compute window (DRAM is otherwise idle here).
__global__ void __launch_bounds__(256) edge_kernel(const float* __restrict__ x,
                                                   const float* __restrict__ ea,
                                                   const int* __restrict__ src,
                                                   const int* __restrict__ tgt,
                                                   const float* __restrict__ Wq,
                                                   const float* __restrict__ bq,
                                                   const float* __restrict__ Wk,
                                                   const float* __restrict__ bk,
                                                   const float* __restrict__ We,
                                                   const float* __restrict__ Wv,
                                                   const float* __restrict__ bv,
                                                   const float* __restrict__ Wfc)
{
    __shared__ float sa[4][16];     // coefA per layer (t fixed per block)
    __shared__ float sp[4][12];     // coefP[0..4], coefQ at [5..9]

    int tid = threadIdx.x;
    int wid = tid >> 5, lane = tid & 31;
    int idx = blockIdx.x * 256 + tid;   // 0 .. T*E-1
    int t = (blockIdx.x * 256) >> 16;   // constant per block (256 | E)

    // Wfc L2 prefetch FIRST: first 4KB of each row = 32 x 128B sectors/row,
    // 16384 rows -> 524288 sectors, 2 per thread across 262144 threads.
    // No dependencies — issue before any compute so the drain overlaps everything.
    {
        int gtid = blockIdx.x * 256 + tid;
#pragma unroll
        for (int k = 0; k < 2; k++) {
            int sec = gtid * 2 + k;
            int row = sec >> 5;
            int s   = sec & 31;
            const char* p = (const char*)Wfc + (size_t)row * 65536 + (size_t)s * 128;
            asm volatile("prefetch.global.L2 [%0];" :: "l"(p));
        }
    }

    if (wid < 4) {
        // coefA for tl = t*4 + wid
        int tl = t * LL + wid;
        const float* wq0 = Wq + (size_t)tl * 2 * HH;
        const float* wq1 = wq0 + HH;
        const float* bqp = bq + (size_t)tl * HH;
        float q0a = wq0[lane], q0b = wq0[lane + 32];
        float q1a = wq1[lane], q1b = wq1[lane + 32];
        float bba = bqp[lane], bbb = bqp[lane + 32];

        const float* Xs[5];
        Xs[0] = Wk + (size_t)tl * 2 * HH;
        Xs[1] = Xs[0] + HH;
        Xs[2] = We + (size_t)tl * 2 * HH;
        Xs[3] = Xs[2] + HH;
        Xs[4] = bk + (size_t)tl * HH;

        float pa[15];
#pragma unroll
        for (int k = 0; k < 5; k++) {
            float xa = Xs[k][lane], xb = Xs[k][lane + 32];
            pa[3*k + 0] = q0a * xa + q0b * xb;
            pa[3*k + 1] = q1a * xa + q1b * xb;
            pa[3*k + 2] = bba * xa + bbb * xb;
        }
#pragma unroll
        for (int off = 16; off > 0; off >>= 1)
#pragma unroll
            for (int i = 0; i < 15; i++)
                pa[i] += __shfl_down_sync(0xffffffffu, pa[i], off);
        if (lane == 0) {
#pragma unroll
            for (int i = 0; i < 15; i++) sa[wid][i] = pa[i];
            sa[wid][15] = 0.0f;
        }
    } else {
        // coefP/Q for tl = t*4 + (wid-4)
        int lw = wid - 4;
        int tl = t * LL + lw;
        const float* Ys[5];
        Ys[0] = Wv + (size_t)tl * 2 * HH;
        Ys[1] = Ys[0] + HH;
        Ys[2] = We + (size_t)tl * 2 * HH;
        Ys[3] = Ys[2] + HH;
        Ys[4] = bv + (size_t)tl * HH;

        float ph[10];
#pragma unroll
        for (int k = 0; k < 5; k++) {
            ph[k]     = Ys[k][lane];            // low half (h<32)
            ph[5 + k] = Ys[k][lane + 32];       // high half
        }
#pragma unroll
        for (int off = 16; off > 0; off >>= 1)
#pragma unroll
            for (int i = 0; i < 10; i++)
                ph[i] += __shfl_down_sync(0xffffffffu, ph[i], off);
        if (lane == 0)
#pragma unroll
            for (int i = 0; i < 10; i++) sp[lw][i] = ph[i];
    }
    __syncthreads();

    int s = src[idx];
    int g = tgt[idx];
    float xs0 = x[2 * s], xs1 = x[2 * s + 1];
    float ea0 = ea[2 * idx], ea1 = ea[2 * idx + 1];
    int tn = t * NN + g;
    float xt0 = x[2 * tn], xt1 = x[2 * tn + 1];

#pragma unroll
    for (int l = 0; l < LL; l++) {
        const float* c = sa[l];
        float A0 = fmaf(c[0],  xt0, fmaf(c[1],  xt1, c[2]));
        float A1 = fmaf(c[3],  xt0, fmaf(c[4],  xt1, c[5]));
        float A2 = fmaf(c[6],  xt0, fmaf(c[7],  xt1, c[8]));
        float A3 = fmaf(c[9],  xt0, fmaf(c[10], xt1, c[11]));
        float A4 = fmaf(c[12], xt0, fmaf(c[13], xt1, c[14]));
        float alpha = (A0 * xs0 + A1 * xs1 + A2 * ea0 + A3 * ea1 + A4) * 0.125f;
        float w = expf(alpha);   // |alpha| is O(1): shift-free softmax is safe

        const float* hh = sp[l];
        float p = fmaf(hh[0], xs0, fmaf(hh[1], xs1, fmaf(hh[2], ea0, fmaf(hh[3], ea1, hh[4]))));
        float q = fmaf(hh[5], xs0, fmaf(hh[6], xs1, fmaf(hh[7], ea0, fmaf(hh[8], ea1, hh[9]))));

        float* sm = &g_sums[((t * LL + l) * NN + g) * 8];
        asm volatile("red.global.add.v4.f32 [%0], {%1, %2, %3, %4};"
                     :: "l"(sm), "f"(w * p), "f"(w * q), "f"(w), "f"(0.0f)
                     : "memory");
    }
}

// ---------------- K2: node pass — normalize, add skip, restore zeros, prefetch more Wfc ----------------
__global__ void __launch_bounds__(256) node_kernel(const float* __restrict__ x,
                                                   const float* __restrict__ Wsk,
                                                   const float* __restrict__ bsk,
                                                   const float* __restrict__ Wfc)
{
    __shared__ float h[8];   // skip coefs: [0..2]={Wsk0,Wsk1,bsk} low half, [3..5]=high half

    int tid = threadIdx.x;
    int idx = blockIdx.x * 256 + tid;   // 0 .. T*L*N-1
    int tl = (blockIdx.x * 256) >> 11;  // constant per block (256 | N)
    int t = tl >> 2;
    int l = tl & 3;
    int n = idx & (NN - 1);

    // Continue the Wfc prefetch (issued first): next 2KB of each row
    // (bytes 4096..6143) = 16 sectors/row x 16384 rows = 262144 sectors,
    // 8 per thread across 32768 threads. 32 MB, placed closest to the GEMV.
    {
#pragma unroll
        for (int k = 0; k < 8; k++) {
            int sec = idx * 8 + k;
            int row = sec >> 4;
            int s   = 32 + (sec & 15);
            const char* p = (const char*)Wfc + (size_t)row * 65536 + (size_t)s * 128;
            asm volatile("prefetch.global.L2 [%0];" :: "l"(p));
        }
    }

    if (tid < 32) {
        int lane = tid;
        const float* Ys[3];
        Ys[0] = Wsk + (size_t)tl * 2 * HH;
        Ys[1] = Ys[0] + HH;
        Ys[2] = bsk + (size_t)tl * HH;

        float ph[6];
#pragma unroll
        for (int k = 0; k < 3; k++) {
            ph[k]     = Ys[k][lane];
            ph[3 + k] = Ys[k][lane + 32];
        }
#pragma unroll
        for (int off = 16; off > 0; off >>= 1)
#pragma unroll
            for (int i = 0; i < 6; i++)
                ph[i] += __shfl_down_sync(0xffffffffu, ph[i], off);
        if (lane == 0)
#pragma unroll
            for (int i = 0; i < 6; i++) h[i] = ph[i];
    }
    __syncthreads();

    float* smp = &g_sums[idx * 8];
    float4 v = *reinterpret_cast<float4*>(smp);   // {sum_wp, sum_wq, sum_w, 0}

    // restore zeros for next replay (only first 16B are ever written)
    *reinterpret_cast<float4*>(smp) = make_float4(0.f, 0.f, 0.f, 0.f);

    float inv = 1.0f / (v.z + 1e-16f);

    int tn = t * NN + n;
    float xt0 = x[2 * tn], xt1 = x[2 * tn + 1];

    float P = v.x * inv + fmaf(h[0], xt0, fmaf(h[1], xt1, h[2]));
    float Q = v.y * inv + fmaf(h[3], xt0, fmaf(h[4], xt1, h[5]));

    int vo = t * (2 * LL * NN) + 2 * (l * NN + n);
    g_val[vo]     = P;
    g_val[vo + 1] = Q;
}

// ---------------- K3: GEMV — unchanged (8 warps x 2 rows, __ldcs) ----------------
__global__ void __launch_bounds__(256) gemv_kernel(const float* __restrict__ Wfc,
                                                   const float* __restrict__ bfc,
                                                   float* __restrict__ out)
{
    const int t = blockIdx.y;
    const int rowBase = blockIdx.x * 16;
    __shared__ float4 sv[1024];                    // 16 KB chunk of val

    int tid = threadIdx.x;
    int lane = tid & 31;
    int w = tid >> 5;
    int r0 = rowBase + w;
    int r1 = rowBase + 8 + w;

    const float4* val4 = reinterpret_cast<const float4*>(g_val + t * (2 * LL * NN));
    const float4* W0 = reinterpret_cast<const float4*>(Wfc + ((size_t)(t * 4096 + r0)) * 16384);
    const float4* W1 = reinterpret_cast<const float4*>(Wfc + ((size_t)(t * 4096 + r1)) * 16384);

    float4 a0 = make_float4(0.f, 0.f, 0.f, 0.f);
    float4 a1 = make_float4(0.f, 0.f, 0.f, 0.f);

#pragma unroll
    for (int c = 0; c < 4; c++) {
        for (int j = tid; j < 1024; j += 256)
            sv[j] = val4[c * 1024 + j];
        __syncthreads();

        const int base = c * 1024;
#pragma unroll 8
        for (int j = lane; j < 1024; j += 32) {
            float4 v  = sv[j];
            float4 w0 = __ldcs(&W0[base + j]);   // streaming: no-reuse 1GB scan
            float4 w1 = __ldcs(&W1[base + j]);
            a0.x = fmaf(w0.x, v.x, a0.x);
            a0.y = fmaf(w0.y, v.y, a0.y);
            a0.z = fmaf(w0.z, v.z, a0.z);
            a0.w = fmaf(w0.w, v.w, a0.w);
            a1.x = fmaf(w1.x, v.x, a1.x);
            a1.y = fmaf(w1.y, v.y, a1.y);
            a1.z = fmaf(w1.z, v.z, a1.z);
            a1.w = fmaf(w1.w, v.w, a1.w);
        }
        __syncthreads();
    }

    float s0 = (a0.x + a0.y) + (a0.z + a0.w);
    float s1 = (a1.x + a1.y) + (a1.z + a1.w);
#pragma unroll
    for (int off = 16; off > 0; off >>= 1) {
        s0 += __shfl_down_sync(0xffffffffu, s0, off);
        s1 += __shfl_down_sync(0xffffffffu, s1, off);
    }
    if (lane == 0) {
        out[t * 4096 + r0] = s0 + bfc[t * 4096 + r0];
        out[t * 4096 + r1] = s1 + bfc[t * 4096 + r1];
    }
}

// ---------------- launch: 3 kernels, single stream ----------------
extern "C" void kernel_launch(void* const* d_in, const int* in_sizes, int n_in,
                              void* d_out, int out_size)
{
    const float* x    = (const float*)d_in[0];
    const float* ea   = (const float*)d_in[1];
    const int*   src  = (const int*)  d_in[2];
    const int*   tgt  = (const int*)  d_in[3];
    const float* Wq   = (const float*)d_in[4];
    const float* bq   = (const float*)d_in[5];
    const float* Wk   = (const float*)d_in[6];
    const float* bk   = (const float*)d_in[7];
    const float* Wv   = (const float*)d_in[8];
    const float* bv   = (const float*)d_in[9];
    const float* We   = (const float*)d_in[10];
    const float* Wsk  = (const float*)d_in[11];
    const float* bsk  = (const float*)d_in[12];
    const float* Wfc  = (const float*)d_in[13];
    const float* bfc  = (const float*)d_in[14];
    float* out = (float*)d_out;

    edge_kernel<<<(TT * EE) / 256, 256>>>(x, ea, src, tgt, Wq, bq, Wk, bk, We, Wv, bv, Wfc);
    node_kernel<<<(TL * NN) / 256, 256>>>(x, Wsk, bsk, Wfc);
    gemv_kernel<<<dim3(256, TT), 256>>>(Wfc, bfc, out);
}